// round 15
// baseline (speedup 1.0000x reference)
#include <cuda_runtime.h>
#include <cooperative_groups.h>
#include <math.h>

namespace cg = cooperative_groups;

#define HW 64
#define NP 4096
#define CK 1024          // elements per block (chunk)
#define THREADS 512      // 2 elements per thread
#define MAXB 32

// per-block partial sums + monotonic ticket (never reset; graph-replay-safe)
__device__ float g_part[MAXB * 8];
__device__ unsigned int g_tick;

__global__ __launch_bounds__(THREADS, 1) __cluster_dims__(8, 1, 1)
void chamfer_kernel(const float* __restrict__ depth,
                    const float* __restrict__ bnd,
                    float* __restrict__ out,
                    float inv_total, int nblk) {
    __shared__ __align__(16) float dbuf[2 * CK];   // sort ping-pong
    __shared__ __align__(16) float s_sorted[CK];   // published sorted chunk (DSMEM)
    __shared__ __align__(16) float s_peer[NP];     // other array's 4 sorted chunks
    __shared__ float swarp[16];

    cg::cluster_group cluster = cg::this_cluster();
    const int t    = threadIdx.x;
    const int lane = t & 31, wid = t >> 5;
    const int blk  = blockIdx.x;
    const int rank = (int)cluster.block_rank();   // 0..7
    const int c    = rank & 3;            // chunk quarter
    const int arr  = rank >> 2;           // 0 = sobel(g), 1 = boundary
    const int b    = blk >> 3;            // batch

    const int i0 = 2 * t;                 // first owned element within chunk
    const int e0 = c * CK + i0;           // within batch array

    // ---- Phase 1: two elements per thread ----
    float v0, v1;
    if (arr == 1) {
        float2 q = *(const float2*)(bnd + b * NP + e0);
        v0 = q.x; v1 = q.y;
    } else {
        const float* d = depth + b * NP;
        int y = e0 >> 6, x0 = e0 & 63;    // x0 multiple of 2
        float p[3][4];                    // rows y-1..y+1, cols x0-1..x0+2
        #pragma unroll
        for (int ry = 0; ry < 3; ry++) {
            int yy = y + ry - 1;
            bool yok = (yy >= 0) & (yy < HW);
            #pragma unroll
            for (int cx = 0; cx < 4; cx++) {
                int xx = x0 + cx - 1;
                bool ok = yok & (xx >= 0) & (xx < HW);
                p[ry][cx] = ok ? d[yy * HW + xx] : 0.0f;
            }
        }
        #pragma unroll
        for (int m = 0; m < 2; m++) {
            float gx = (p[0][m] - p[0][m + 2]) + 2.0f * (p[1][m] - p[1][m + 2]) + (p[2][m] - p[2][m + 2]);
            float gy = (p[0][m] + 2.0f * p[0][m + 1] + p[0][m + 2])
                     - (p[2][m] + 2.0f * p[2][m + 1] + p[2][m + 2]);
            float g = sqrtf(gx * gx + gy * gy + 1e-8f);
            if (m == 0) v0 = g; else v1 = g;
        }
    }

    // ---- Phase 2: ascending bitonic sort of 1024, 2 elems/thread ----
    // Partner thread for j>=2 is t^(j/2): j<=32 -> lane distance <=16, in-warp
    // shfl; j>=64 -> cross-warp, smem float2 exchange (10 steps, dbuf, 1 bar
    // each). j=1 in-thread. (R8/R9 lesson: never shfl across warps.)
    int pbuf = 0;
    #pragma unroll
    for (int k = 2; k <= CK; k <<= 1) {
        #pragma unroll
        for (int j = k >> 1; j >= 1; j >>= 1) {
            if (j >= 64) {
                float* buf = dbuf + pbuf * CK;
                *(float2*)&buf[i0] = make_float2(v0, v1);
                __syncthreads();
                bool keepMin = ((i0 & j) == 0) == ((i0 & k) == 0);
                float2 o = *(float2*)&buf[i0 ^ j];   // j even -> 8B aligned
                v0 = keepMin ? fminf(v0, o.x) : fmaxf(v0, o.x);
                v1 = keepMin ? fminf(v1, o.y) : fmaxf(v1, o.y);
                pbuf ^= 1;
            } else if (j >= 2) {
                bool keepMin = ((i0 & j) == 0) == ((i0 & k) == 0);
                float o0 = __shfl_xor_sync(0xffffffffu, v0, j >> 1);
                float o1 = __shfl_xor_sync(0xffffffffu, v1, j >> 1);
                v0 = keepMin ? fminf(v0, o0) : fmaxf(v0, o0);
                v1 = keepMin ? fminf(v1, o1) : fmaxf(v1, o1);
            } else {                       // j == 1: in-thread pair
                bool up = ((i0 & k) == 0);
                float lo = fminf(v0, v1), hi = fmaxf(v0, v1);
                v0 = up ? lo : hi;
                v1 = up ? hi : lo;
            }
        }
    }

    // publish sorted chunk (v0,v1 stay as this thread's queries; multiset
    // unchanged, final sum permutation-invariant)
    *(float2*)&s_sorted[i0] = make_float2(v0, v1);

    // ---- Phase 3: cluster barrier (orders smem writes for DSMEM readers) ----
    cluster.sync();

    // ---- Phase 4: pull the OTHER array's 4 sorted chunks via DSMEM ----
    {
        int ch = t >> 7;                    // 0..3 (128 threads per chunk)
        int q  = (t & 127) * 8;             // 8 floats per thread (2x float4)
        const float* peer = cluster.map_shared_rank(s_sorted, (arr ^ 1) * 4 + ch);
        float* dst = s_peer + (ch << 10);
        *(float4*)(dst + q)     = *(const float4*)(peer + q);
        *(float4*)(dst + q + 4) = *(const float4*)(peer + q + 4);
    }
    cluster.sync();   // no CTA exits while peers still read its smem

    // ---- Phase 5: 8 interleaved searches (2 queries x 4 chunks, 10 levels) ----
    float acc = 0.0f;
    #pragma unroll
    for (int m = 0; m < 2; m++) {
        const float x = m ? v1 : v0;
        float dmin = 3.4e38f;
        #pragma unroll
        for (int ch = 0; ch < 4; ch++) {
            const float* T = s_peer + (ch << 10);
            int pos = 0;                  // branchless lower_bound, saturates at CK-1
            #pragma unroll
            for (int s = CK / 2; s >= 1; s >>= 1) {
                if (T[pos + s - 1] < x) pos += s;
            }
            // x > all of chunk: pos=CK-1, T[pos]<x, fabsf = dist to chunk max
            float dd = fabsf(T[pos] - x);
            if (pos > 0) dd = fminf(dd, x - T[pos - 1]);
            dmin = fminf(dmin, dd);
        }
        acc += dmin;
    }

    // ---- Phase 6: block reduce (16 warps); ticket finalize (replay-safe) ----
    #pragma unroll
    for (int o = 16; o > 0; o >>= 1) acc += __shfl_xor_sync(0xffffffffu, acc, o);
    if (lane == 0) swarp[wid] = acc;
    __syncthreads();
    if (t < 32) {
        float z = (t < 16) ? swarp[t] : 0.0f;
        #pragma unroll
        for (int o = 8; o > 0; o >>= 1) z += __shfl_xor_sync(0xffffffffu, z, o);
        if (t == 0) {
            g_part[blk] = z;
            __threadfence();
            unsigned int tk = atomicAdd(&g_tick, 1u);
            if ((tk % (unsigned)nblk) == (unsigned)(nblk - 1)) {
                __threadfence();      // all partials of this launch visible
                float s = 0.0f;
                for (int i2 = 0; i2 < nblk; i2++)
                    s += ((volatile float*)g_part)[i2];
                out[0] = s * inv_total;   // overwrites poison on every replay
            }
        }
    }
}

extern "C" void kernel_launch(void* const* d_in, const int* in_sizes, int n_in,
                              void* d_out, int out_size) {
    const float* depth = (const float*)d_in[0];
    const float* bnd   = (const float*)d_in[1];
    float* out = (float*)d_out;

    int B = in_sizes[0] / NP;
    if (B > MAXB) B = MAXB;
    int nblk = B * 8;                 // multiple of cluster size 8
    float inv_total = 1.0f / (float)(B * NP);

    chamfer_kernel<<<nblk, THREADS>>>(depth, bnd, out, inv_total, nblk);
}

// round 16
// speedup vs baseline: 1.0025x; 1.0025x over previous
#include <cuda_runtime.h>
#include <cooperative_groups.h>
#include <math.h>

namespace cg = cooperative_groups;

#define HW 64
#define NP 4096
#define CK 2048          // elements per block (chunk)
#define THREADS 1024     // 2 elements per thread
#define MAXB 32

// per-block partial sums + monotonic ticket (never reset; graph-replay-safe)
__device__ float g_part[MAXB * 4];
__device__ unsigned int g_tick;

__global__ __launch_bounds__(THREADS, 1) __cluster_dims__(4, 1, 1)
void chamfer_kernel(const float* __restrict__ depth,
                    const float* __restrict__ bnd,
                    float* __restrict__ out,
                    float inv_total, int nblk) {
    __shared__ __align__(16) float dbuf[2 * CK];   // sort ping-pong (16 KB)
    __shared__ __align__(16) float s_sorted[CK];   // published sorted chunk (8 KB, DSMEM)
    __shared__ __align__(16) float s_peer[NP];     // other array's 2 sorted chunks (16 KB)
    __shared__ float swarp[32];

    cg::cluster_group cluster = cg::this_cluster();
    const int t    = threadIdx.x;
    const int lane = t & 31, wid = t >> 5;
    const int blk  = blockIdx.x;
    const int rank = (int)cluster.block_rank();   // 0..3
    const int c    = rank & 1;            // chunk half
    const int arr  = rank >> 1;           // 0 = sobel(g), 1 = boundary
    const int b    = blk >> 2;            // batch

    const int i0 = 2 * t;                 // first owned element within chunk
    const int e0 = c * CK + i0;           // within batch array

    // ---- Phase 1: two elements per thread ----
    float v0, v1;
    if (arr == 1) {
        float2 q = *(const float2*)(bnd + b * NP + e0);
        v0 = q.x; v1 = q.y;
    } else {
        const float* d = depth + b * NP;
        int y = e0 >> 6, x0 = e0 & 63;    // x0 multiple of 2
        float p[3][4];                    // rows y-1..y+1, cols x0-1..x0+2
        #pragma unroll
        for (int ry = 0; ry < 3; ry++) {
            int yy = y + ry - 1;
            bool yok = (yy >= 0) & (yy < HW);
            #pragma unroll
            for (int cx = 0; cx < 4; cx++) {
                int xx = x0 + cx - 1;
                bool ok = yok & (xx >= 0) & (xx < HW);
                p[ry][cx] = ok ? d[yy * HW + xx] : 0.0f;
            }
        }
        #pragma unroll
        for (int m = 0; m < 2; m++) {
            float gx = (p[0][m] - p[0][m + 2]) + 2.0f * (p[1][m] - p[1][m + 2]) + (p[2][m] - p[2][m + 2]);
            float gy = (p[0][m] + 2.0f * p[0][m + 1] + p[0][m + 2])
                     - (p[2][m] + 2.0f * p[2][m + 1] + p[2][m + 2]);
            float g = sqrtf(gx * gx + gy * gy + 1e-8f);
            if (m == 0) v0 = g; else v1 = g;
        }
    }

    // ---- Phase 2: ascending bitonic sort of 2048, 2 elems/thread ----
    // Partner thread for j>=2 is t^(j/2): j<=32 -> lane distance <=16, in-warp
    // shfl; j>=64 -> cross-warp, smem float2 exchange (15 steps, dbuf, one
    // full __syncthreads each). j=1 in-thread. (R8/R9: never shfl across warps.)
    int pbuf = 0;
    #pragma unroll
    for (int k = 2; k <= CK; k <<= 1) {
        #pragma unroll
        for (int j = k >> 1; j >= 1; j >>= 1) {
            if (j >= 64) {
                float* buf = dbuf + pbuf * CK;
                *(float2*)&buf[i0] = make_float2(v0, v1);
                __syncthreads();
                bool keepMin = ((i0 & j) == 0) == ((i0 & k) == 0);
                float2 o = *(float2*)&buf[i0 ^ j];   // j even -> 8B aligned
                v0 = keepMin ? fminf(v0, o.x) : fmaxf(v0, o.x);
                v1 = keepMin ? fminf(v1, o.y) : fmaxf(v1, o.y);
                pbuf ^= 1;
            } else if (j >= 2) {
                bool keepMin = ((i0 & j) == 0) == ((i0 & k) == 0);
                float o0 = __shfl_xor_sync(0xffffffffu, v0, j >> 1);
                float o1 = __shfl_xor_sync(0xffffffffu, v1, j >> 1);
                v0 = keepMin ? fminf(v0, o0) : fmaxf(v0, o0);
                v1 = keepMin ? fminf(v1, o1) : fmaxf(v1, o1);
            } else {                       // j == 1: in-thread pair
                bool up = ((i0 & k) == 0);
                float lo = fminf(v0, v1), hi = fmaxf(v0, v1);
                v0 = up ? lo : hi;
                v1 = up ? hi : lo;
            }
        }
    }

    // publish sorted chunk (v0,v1 stay as this thread's queries; multiset
    // unchanged, final sum permutation-invariant)
    *(float2*)&s_sorted[i0] = make_float2(v0, v1);

    // ---- Phase 3: cluster barrier (orders smem writes for DSMEM readers) ----
    cluster.sync();

    // ---- Phase 4: pull the OTHER array's 2 sorted chunks via DSMEM ----
    {
        int ch = t >> 9;                    // 0..1 (512 threads per chunk)
        int q  = (t & 511) * 4;             // one float4 per thread
        const float* peer = cluster.map_shared_rank(s_sorted, (arr ^ 1) * 2 + ch);
        *(float4*)(s_peer + (ch << 11) + q) = *(const float4*)(peer + q);
    }
    cluster.sync();   // no CTA exits while peers still read its smem

    // ---- Phase 5: 4 interleaved searches (2 queries x 2 chunks, 11 levels) ----
    float acc = 0.0f;
    #pragma unroll
    for (int m = 0; m < 2; m++) {
        const float x = m ? v1 : v0;
        float dmin = 3.4e38f;
        #pragma unroll
        for (int ch = 0; ch < 2; ch++) {
            const float* T = s_peer + (ch << 11);
            int pos = 0;                  // branchless lower_bound, saturates at CK-1
            #pragma unroll
            for (int s = CK / 2; s >= 1; s >>= 1) {
                if (T[pos + s - 1] < x) pos += s;
            }
            // x > all of chunk: pos=CK-1, T[pos]<x, fabsf = dist to chunk max
            float dd = fabsf(T[pos] - x);
            if (pos > 0) dd = fminf(dd, x - T[pos - 1]);
            dmin = fminf(dmin, dd);
        }
        acc += dmin;
    }

    // ---- Phase 6: block reduce (32 warps); ticket finalize (replay-safe) ----
    #pragma unroll
    for (int o = 16; o > 0; o >>= 1) acc += __shfl_xor_sync(0xffffffffu, acc, o);
    if (lane == 0) swarp[wid] = acc;
    __syncthreads();
    if (t < 32) {
        float z = swarp[t];           // exactly 32 warps
        #pragma unroll
        for (int o = 16; o > 0; o >>= 1) z += __shfl_xor_sync(0xffffffffu, z, o);
        if (t == 0) {
            g_part[blk] = z;
            __threadfence();
            unsigned int tk = atomicAdd(&g_tick, 1u);
            if ((tk % (unsigned)nblk) == (unsigned)(nblk - 1)) {
                __threadfence();      // all partials of this launch visible
                float s = 0.0f;
                for (int i2 = 0; i2 < nblk; i2++)
                    s += ((volatile float*)g_part)[i2];
                out[0] = s * inv_total;   // overwrites poison on every replay
            }
        }
    }
}

extern "C" void kernel_launch(void* const* d_in, const int* in_sizes, int n_in,
                              void* d_out, int out_size) {
    const float* depth = (const float*)d_in[0];
    const float* bnd   = (const float*)d_in[1];
    float* out = (float*)d_out;

    int B = in_sizes[0] / NP;
    if (B > MAXB) B = MAXB;
    int nblk = B * 4;                 // multiple of cluster size 4
    float inv_total = 1.0f / (float)(B * NP);

    chamfer_kernel<<<nblk, THREADS>>>(depth, bnd, out, inv_total, nblk);
}